// round 1
// baseline (speedup 1.0000x reference)
#include <cuda_runtime.h>
#include <math.h>

#define MAXN 100000

// Scratch (allocation-free: __device__ globals)
__device__ float g_agg1[MAXN * 128]; // [agg(inputs) | agg(state)] per node
__device__ float g_agg2[MAXN * 64];  // agg(r*state) per node
__device__ float g_deg[MAXN];
__device__ float g_rs[MAXN * 64];    // r * state
__device__ float g_u[MAXN * 64];     // update gate u

__device__ __forceinline__ void red_add_v4(float* p, float4 v) {
    asm volatile("red.global.add.v4.f32 [%0], {%1,%2,%3,%4};"
                 :: "l"(p), "f"(v.x), "f"(v.y), "f"(v.z), "f"(v.w) : "memory");
}

// ---------------------------------------------------------------------------
// Stage-1 scatter: one warp per edge. Lanes 0-15 gather inputs[src] (64 f),
// lanes 16-31 gather state[src]; vector red.add into g_agg1[dst*128 + lane*4].
// ---------------------------------------------------------------------------
__global__ void scatter1_kernel(const float* __restrict__ inputs,
                                const float* __restrict__ state,
                                const int* __restrict__ src,
                                const int* __restrict__ dst, int E) {
    int gid = blockIdx.x * blockDim.x + threadIdx.x;
    int e = gid >> 5;
    int lane = gid & 31;
    if (e >= E) return;
    int s = src[e], d = dst[e];
    const float* rb = (lane < 16) ? (inputs + s * 64 + lane * 4)
                                  : (state + s * 64 + (lane - 16) * 4);
    float4 v = *(const float4*)rb;
    red_add_v4(g_agg1 + d * 128 + lane * 4, v);
    if (lane == 0) atomicAdd(&g_deg[d], 1.0f);
}

// ---------------------------------------------------------------------------
// Stage-2 scatter: half-warp per edge over g_rs (64 f per row).
// ---------------------------------------------------------------------------
__global__ void scatter2_kernel(const int* __restrict__ src,
                                const int* __restrict__ dst, int E) {
    int gid = blockIdx.x * blockDim.x + threadIdx.x;
    int e = gid >> 4;
    int l = gid & 15;
    if (e >= E) return;
    int s = src[e], d = dst[e];
    float4 v = *(const float4*)(g_rs + s * 64 + l * 4);
    red_add_v4(g_agg2 + d * 64 + l * 4, v);
}

// ---------------------------------------------------------------------------
// Gate GEMM: h = sigmoid([xs | agg1/deg] @ [Wg_self; Wg_neigh] + bg + gate_bias)
// Writes g_rs = r*state (cols 0-63) and g_u = u (cols 64-127).
// Block = 8 warps; warp handles 8 nodes x 128 cols (lane = 4 cols).
// ---------------------------------------------------------------------------
__global__ void __launch_bounds__(256, 1) gate_kernel(
    const float* __restrict__ inputs, const float* __restrict__ state,
    const float* __restrict__ Wself, const float* __restrict__ Wneigh,
    const float* __restrict__ bg, const float* __restrict__ gbias, int N) {
    extern __shared__ float sm[];
    float* Wsh = sm;             // 256 x 128
    float* xb = sm + 256 * 128;  // 8 warps * 8 nodes * 256
    int tid = threadIdx.x, lane = tid & 31, warp = tid >> 5;

    for (int i = tid; i < 128 * 128; i += 256) {
        Wsh[i] = Wself[i];
        Wsh[i + 128 * 128] = Wneigh[i];
    }
    __syncthreads();

    int nbase = blockIdx.x * 64 + warp * 8;
    float* xw = xb + warp * (8 * 256);
    #pragma unroll
    for (int m = 0; m < 8; m++) {
        int node = nbase + m;
        if (node < N) {
            float id = 1.0f / fmaxf(g_deg[node], 1.0f);
            for (int k = lane; k < 256; k += 32) {
                float v;
                if (k < 64)        v = inputs[node * 64 + k];
                else if (k < 128)  v = state[node * 64 + (k - 64)];
                else               v = g_agg1[node * 128 + (k - 128)] * id;
                xw[m * 256 + k] = v;
            }
        } else {
            for (int k = lane; k < 256; k += 32) xw[m * 256 + k] = 0.0f;
        }
    }
    __syncwarp();

    float4 acc[8];
    #pragma unroll
    for (int m = 0; m < 8; m++) acc[m] = make_float4(0.f, 0.f, 0.f, 0.f);

    const float4* W4 = (const float4*)Wsh;
    #pragma unroll 4
    for (int k = 0; k < 256; k++) {
        float4 w = W4[k * 32 + lane];
        #pragma unroll
        for (int m = 0; m < 8; m++) {
            float x = xw[m * 256 + k];
            acc[m].x = fmaf(x, w.x, acc[m].x);
            acc[m].y = fmaf(x, w.y, acc[m].y);
            acc[m].z = fmaf(x, w.z, acc[m].z);
            acc[m].w = fmaf(x, w.w, acc[m].w);
        }
    }

    int col = lane * 4;
    float4 bb;
    bb.x = bg[col + 0] + gbias[col + 0];
    bb.y = bg[col + 1] + gbias[col + 1];
    bb.z = bg[col + 2] + gbias[col + 2];
    bb.w = bg[col + 3] + gbias[col + 3];

    #pragma unroll
    for (int m = 0; m < 8; m++) {
        int node = nbase + m;
        if (node >= N) break;
        float4 a = acc[m];
        a.x = 1.0f / (1.0f + __expf(-(a.x + bb.x)));
        a.y = 1.0f / (1.0f + __expf(-(a.y + bb.y)));
        a.z = 1.0f / (1.0f + __expf(-(a.z + bb.z)));
        a.w = 1.0f / (1.0f + __expf(-(a.w + bb.w)));
        if (lane < 16) {  // r -> r*state
            float4 st = *(const float4*)(state + node * 64 + col);
            float4 r = make_float4(a.x * st.x, a.y * st.y, a.z * st.z, a.w * st.w);
            *(float4*)(g_rs + node * 64 + col) = r;
        } else {          // u
            *(float4*)(g_u + node * 64 + (col - 64)) = a;
        }
    }
}

// ---------------------------------------------------------------------------
// Candidate GEMM + final GRU update:
// c = tanh([inputs | rs | agg(inputs)/deg | agg(rs)/deg] @ [Wc_self; Wc_neigh]
//          + bc + cand_bias)
// out = u*state + (1-u)*c
// Block = 8 warps; warp handles 16 nodes x 64 cols (half-warp = 8 nodes).
// ---------------------------------------------------------------------------
__global__ void __launch_bounds__(256, 1) cand_kernel(
    const float* __restrict__ inputs, const float* __restrict__ state,
    const float* __restrict__ Wself, const float* __restrict__ Wneigh,
    const float* __restrict__ bc, const float* __restrict__ cbias,
    float* __restrict__ out, int N) {
    extern __shared__ float sm[];
    float* Wsh = sm;            // 256 x 64
    float* xb = sm + 256 * 64;  // 8 warps * 16 nodes * 256
    int tid = threadIdx.x, lane = tid & 31, warp = tid >> 5;
    int lane16 = lane & 15, grp = lane >> 4;

    for (int i = tid; i < 128 * 64; i += 256) {
        Wsh[i] = Wself[i];
        Wsh[i + 128 * 64] = Wneigh[i];
    }
    __syncthreads();

    int nbase = blockIdx.x * 128 + warp * 16;
    float* xw = xb + warp * (16 * 256);
    for (int m = 0; m < 16; m++) {
        int node = nbase + m;
        if (node < N) {
            float id = 1.0f / fmaxf(g_deg[node], 1.0f);
            for (int k = lane; k < 256; k += 32) {
                float v;
                if (k < 64)        v = inputs[node * 64 + k];
                else if (k < 128)  v = g_rs[node * 64 + (k - 64)];
                else if (k < 192)  v = g_agg1[node * 128 + (k - 128)] * id; // agg(inputs)
                else               v = g_agg2[node * 64 + (k - 192)] * id;  // agg(rs)
                xw[m * 256 + k] = v;
            }
        } else {
            for (int k = lane; k < 256; k += 32) xw[m * 256 + k] = 0.0f;
        }
    }
    __syncwarp();

    float4 acc[8];
    #pragma unroll
    for (int m = 0; m < 8; m++) acc[m] = make_float4(0.f, 0.f, 0.f, 0.f);

    const float4* W4 = (const float4*)Wsh;
    #pragma unroll 4
    for (int k = 0; k < 256; k++) {
        float4 w = W4[k * 16 + lane16];
        #pragma unroll
        for (int m = 0; m < 8; m++) {
            float x = xw[(grp * 8 + m) * 256 + k];
            acc[m].x = fmaf(x, w.x, acc[m].x);
            acc[m].y = fmaf(x, w.y, acc[m].y);
            acc[m].z = fmaf(x, w.z, acc[m].z);
            acc[m].w = fmaf(x, w.w, acc[m].w);
        }
    }

    int col = lane16 * 4;
    float4 bb;
    bb.x = bc[col + 0] + cbias[col + 0];
    bb.y = bc[col + 1] + cbias[col + 1];
    bb.z = bc[col + 2] + cbias[col + 2];
    bb.w = bc[col + 3] + cbias[col + 3];

    #pragma unroll
    for (int m = 0; m < 8; m++) {
        int node = nbase + grp * 8 + m;
        if (node >= N) break;
        float4 a = acc[m];
        a.x = tanhf(a.x + bb.x);
        a.y = tanhf(a.y + bb.y);
        a.z = tanhf(a.z + bb.z);
        a.w = tanhf(a.w + bb.w);
        float4 u4 = *(const float4*)(g_u + node * 64 + col);
        float4 st = *(const float4*)(state + node * 64 + col);
        float4 o;
        o.x = u4.x * st.x + (1.0f - u4.x) * a.x;
        o.y = u4.y * st.y + (1.0f - u4.y) * a.y;
        o.z = u4.z * st.z + (1.0f - u4.z) * a.z;
        o.w = u4.w * st.w + (1.0f - u4.w) * a.w;
        *(float4*)(out + node * 64 + col) = o;
    }
}

extern "C" void kernel_launch(void* const* d_in, const int* in_sizes, int n_in,
                              void* d_out, int out_size) {
    const float* inputs    = (const float*)d_in[0];
    const float* state     = (const float*)d_in[1];
    const int*   src       = (const int*)d_in[2];
    const int*   dst       = (const int*)d_in[3];
    const float* Wg_self   = (const float*)d_in[4];
    const float* Wg_neigh  = (const float*)d_in[5];
    const float* bg        = (const float*)d_in[6];
    const float* Wc_self   = (const float*)d_in[7];
    const float* Wc_neigh  = (const float*)d_in[8];
    const float* bc        = (const float*)d_in[9];
    const float* gate_bias = (const float*)d_in[10];
    const float* cand_bias = (const float*)d_in[11];
    float* out = (float*)d_out;

    int N = in_sizes[0] / 64;
    int E = in_sizes[2];

    void *p_agg1, *p_agg2, *p_deg;
    cudaGetSymbolAddress(&p_agg1, g_agg1);
    cudaGetSymbolAddress(&p_agg2, g_agg2);
    cudaGetSymbolAddress(&p_deg, g_deg);
    cudaMemsetAsync(p_agg1, 0, (size_t)N * 128 * sizeof(float));
    cudaMemsetAsync(p_agg2, 0, (size_t)N * 64 * sizeof(float));
    cudaMemsetAsync(p_deg, 0, (size_t)N * sizeof(float));

    const int SMEM = 196608;  // 192 KB dynamic smem for both GEMM kernels
    cudaFuncSetAttribute(gate_kernel, cudaFuncAttributeMaxDynamicSharedMemorySize, SMEM);
    cudaFuncSetAttribute(cand_kernel, cudaFuncAttributeMaxDynamicSharedMemorySize, SMEM);

    {
        long long thr = (long long)E * 32;
        int blocks = (int)((thr + 255) / 256);
        scatter1_kernel<<<blocks, 256>>>(inputs, state, src, dst, E);
    }
    {
        int blocks = (N + 63) / 64;
        gate_kernel<<<blocks, 256, SMEM>>>(inputs, state, Wg_self, Wg_neigh,
                                           bg, gate_bias, N);
    }
    {
        long long thr = (long long)E * 16;
        int blocks = (int)((thr + 255) / 256);
        scatter2_kernel<<<blocks, 256>>>(src, dst, E);
    }
    {
        int blocks = (N + 127) / 128;
        cand_kernel<<<blocks, 256, SMEM>>>(inputs, state, Wc_self, Wc_neigh,
                                           bc, cand_bias, out, N);
    }
}

// round 3
// speedup vs baseline: 2.1456x; 2.1456x over previous
#include <cuda_runtime.h>
#include <cuda_bf16.h>
#include <math.h>
#include <stdint.h>

#define MAXN 100000

// ---------------------------------------------------------------------------
// Scratch (__device__ globals; allocation-free)
// ---------------------------------------------------------------------------
__device__ float g_agg1[MAXN * 128]; // [agg(inputs) | agg(state)]
__device__ float g_agg2[MAXN * 64];  // agg(r*state)
__device__ float g_deg[MAXN];
__device__ float g_rs[MAXN * 64];    // r * state
__device__ float g_u[MAXN * 64];     // update gate u
// Pre-packed B fragments in mma.sync per-lane layout.
// [kt][nt][lane] -> {b_hi0, b_hi1, b_mid0, b_mid1}
__device__ uint4 g_fragBg[16 * 16 * 32]; // gate:  K=256 (16 kt), N=128 (16 nt)
__device__ uint4 g_fragBc[16 * 8 * 32];  // cand:  K=256 (16 kt), N=64  (8 nt)

// ---------------------------------------------------------------------------
// Helpers
// ---------------------------------------------------------------------------
__device__ __forceinline__ uint32_t pack_bf2(__nv_bfloat16 lo, __nv_bfloat16 hi) {
    __nv_bfloat162 v(lo, hi);
    return *(uint32_t*)&v;
}
__device__ __forceinline__ void split2(float2 p, uint32_t& h, uint32_t& m) {
    __nv_bfloat16 hx = __float2bfloat16(p.x);
    __nv_bfloat16 hy = __float2bfloat16(p.y);
    __nv_bfloat16 mx = __float2bfloat16(p.x - __bfloat162float(hx));
    __nv_bfloat16 my = __float2bfloat16(p.y - __bfloat162float(hy));
    h = pack_bf2(hx, hy);
    m = pack_bf2(mx, my);
}
__device__ __forceinline__ void mma_bf16(float* d, const uint32_t* a,
                                         uint32_t b0, uint32_t b1) {
    asm volatile(
        "mma.sync.aligned.m16n8k16.row.col.f32.bf16.bf16.f32 "
        "{%0,%1,%2,%3}, {%4,%5,%6,%7}, {%8,%9}, {%0,%1,%2,%3};"
        : "+f"(d[0]), "+f"(d[1]), "+f"(d[2]), "+f"(d[3])
        : "r"(a[0]), "r"(a[1]), "r"(a[2]), "r"(a[3]), "r"(b0), "r"(b1));
}
__device__ __forceinline__ void red_add_v4(float* p, float4 v) {
    asm volatile("red.global.add.v4.f32 [%0], {%1,%2,%3,%4};"
                 :: "l"(p), "f"(v.x), "f"(v.y), "f"(v.z), "f"(v.w) : "memory");
}

// ---------------------------------------------------------------------------
// Scatter kernels
// ---------------------------------------------------------------------------
__global__ void scatter1_kernel(const float* __restrict__ inputs,
                                const float* __restrict__ state,
                                const int* __restrict__ src,
                                const int* __restrict__ dst, int E) {
    int gid = blockIdx.x * blockDim.x + threadIdx.x;
    int e = gid >> 5, lane = gid & 31;
    if (e >= E) return;
    int s = src[e], d = dst[e];
    const float* rb = (lane < 16) ? (inputs + s * 64 + lane * 4)
                                  : (state + s * 64 + (lane - 16) * 4);
    float4 v = *(const float4*)rb;
    red_add_v4(g_agg1 + d * 128 + lane * 4, v);
    if (lane == 0) atomicAdd(&g_deg[d], 1.0f);
}
__global__ void scatter2_kernel(const int* __restrict__ src,
                                const int* __restrict__ dst, int E) {
    int gid = blockIdx.x * blockDim.x + threadIdx.x;
    int e = gid >> 4, l = gid & 15;
    if (e >= E) return;
    int s = src[e], d = dst[e];
    float4 v = *(const float4*)(g_rs + s * 64 + l * 4);
    red_add_v4(g_agg2 + d * 64 + l * 4, v);
}

// ---------------------------------------------------------------------------
// Weight prep: pack W columns into mma.sync B-fragment per-lane layout,
// bf16 hi/mid split. One thread per (kt, nt, lane).
//   B[k][n]: k<128 -> Wself[k*HW+n], else Wneigh[(k-128)*HW+n]
//   lane: g = lane>>2 (n = nt*8+g), t = lane&3 (k = kt*16 + t*2 + {0,1,8,9})
// ---------------------------------------------------------------------------
__global__ void prep_weights(const float* __restrict__ Wg_self,
                             const float* __restrict__ Wg_neigh,
                             const float* __restrict__ Wc_self,
                             const float* __restrict__ Wc_neigh) {
    int i = blockIdx.x * blockDim.x + threadIdx.x;
    if (i >= 12288) return;
    bool isGate = i < 8192;
    int j = isGate ? i : (i - 8192);
    int lane = j & 31, tile = j >> 5;
    int g = lane >> 2, t = lane & 3;
    int NT = isGate ? 16 : 8;
    int kt = tile / NT, nt = tile % NT;
    int n = nt * 8 + g;
    int HW = isGate ? 128 : 64;
    const float* Wself  = isGate ? Wg_self : Wc_self;
    const float* Wneigh = isGate ? Wg_neigh : Wc_neigh;
    int k0 = kt * 16 + t * 2;
    float w[4];
    int ks[4] = {k0, k0 + 1, k0 + 8, k0 + 9};
    #pragma unroll
    for (int q = 0; q < 4; q++) {
        int k = ks[q];
        w[q] = (k < 128) ? Wself[k * HW + n] : Wneigh[(k - 128) * HW + n];
    }
    uint32_t h01, m01, h89, m89;
    split2(make_float2(w[0], w[1]), h01, m01);
    split2(make_float2(w[2], w[3]), h89, m89);
    uint4 f = make_uint4(h01, h89, m01, m89);
    if (isGate) g_fragBg[tile * 32 + lane] = f;
    else        g_fragBc[tile * 32 + lane] = f;
}

// ---------------------------------------------------------------------------
// X-row element loaders (float2 at even col), with deg scaling for agg parts
// ---------------------------------------------------------------------------
__device__ __forceinline__ float2 loadXg(const float* __restrict__ inputs,
                                         const float* __restrict__ state,
                                         int row, int k, float id, int N) {
    if (row >= N) return make_float2(0.f, 0.f);
    if (k < 64)  return *(const float2*)(inputs + row * 64 + k);
    if (k < 128) return *(const float2*)(state + row * 64 + (k - 64));
    float2 a = *(const float2*)(g_agg1 + row * 128 + (k - 128));
    return make_float2(a.x * id, a.y * id);
}
__device__ __forceinline__ float2 loadXc(const float* __restrict__ inputs,
                                         int row, int k, float id, int N) {
    if (row >= N) return make_float2(0.f, 0.f);
    if (k < 64)  return *(const float2*)(inputs + row * 64 + k);
    if (k < 128) return *(const float2*)(g_rs + row * 64 + (k - 64));
    if (k < 192) {
        float2 a = *(const float2*)(g_agg1 + row * 128 + (k - 128));
        return make_float2(a.x * id, a.y * id);
    }
    float2 a = *(const float2*)(g_agg2 + row * 64 + (k - 192));
    return make_float2(a.x * id, a.y * id);
}

// ---------------------------------------------------------------------------
// Gate GEMM: h = sigmoid(X[128x256] @ Wg + bg + gbias)
// X = [inputs | state | agg1/deg]. Writes g_rs = r*state, g_u = u.
// Block 256 thr = 8 warps; warp w -> rows nbase + w*16 .. +15, all 128 cols.
// ---------------------------------------------------------------------------
__global__ void __launch_bounds__(256) gate_gemm(
    const float* __restrict__ inputs, const float* __restrict__ state,
    const float* __restrict__ bg, const float* __restrict__ gbias, int N) {
    int tid = threadIdx.x, lane = tid & 31, warp = tid >> 5;
    int g = lane >> 2, t = lane & 3;
    int nbase = blockIdx.x * 128;
    int row0 = nbase + warp * 16 + g;
    int row1 = row0 + 8;
    float id0 = (row0 < N) ? 1.0f / fmaxf(g_deg[row0], 1.0f) : 0.f;
    float id1 = (row1 < N) ? 1.0f / fmaxf(g_deg[row1], 1.0f) : 0.f;

    float acc[16][4];
    #pragma unroll
    for (int nt = 0; nt < 16; nt++)
        #pragma unroll
        for (int q = 0; q < 4; q++) acc[nt][q] = 0.f;

    #pragma unroll
    for (int kt = 0; kt < 16; kt++) {
        int kk = kt * 16 + t * 2;
        float2 p00 = loadXg(inputs, state, row0, kk,     id0, N);
        float2 p10 = loadXg(inputs, state, row1, kk,     id1, N);
        float2 p01 = loadXg(inputs, state, row0, kk + 8, id0, N);
        float2 p11 = loadXg(inputs, state, row1, kk + 8, id1, N);
        uint32_t ah[4], am[4];
        split2(p00, ah[0], am[0]);
        split2(p10, ah[1], am[1]);
        split2(p01, ah[2], am[2]);
        split2(p11, ah[3], am[3]);
        const uint4* fb = g_fragBg + (kt * 16) * 32 + lane;
        #pragma unroll
        for (int nt = 0; nt < 16; nt++) {
            uint4 f = __ldg(fb + nt * 32);
            mma_bf16(acc[nt], ah, f.x, f.y);   // hi * hi
            mma_bf16(acc[nt], ah, f.z, f.w);   // hi * mid
            mma_bf16(acc[nt], am, f.x, f.y);   // mid * hi
        }
    }

    // Epilogue: lane holds cols nt*8 + t*2 (+1) for rows row0, row1
    #pragma unroll
    for (int nt = 0; nt < 16; nt++) {
        int c0 = nt * 8 + t * 2;
        float b0 = __ldg(bg + c0) + __ldg(gbias + c0);
        float b1 = __ldg(bg + c0 + 1) + __ldg(gbias + c0 + 1);
        #pragma unroll
        for (int rr = 0; rr < 2; rr++) {
            int row = rr ? row1 : row0;
            if (row >= N) continue;
            float v0 = acc[nt][rr * 2 + 0] + b0;
            float v1 = acc[nt][rr * 2 + 1] + b1;
            v0 = 1.0f / (1.0f + __expf(-v0));
            v1 = 1.0f / (1.0f + __expf(-v1));
            if (c0 < 64) {  // r -> r*state
                float2 st = *(const float2*)(state + row * 64 + c0);
                *(float2*)(g_rs + row * 64 + c0) = make_float2(v0 * st.x, v1 * st.y);
            } else {        // u
                *(float2*)(g_u + row * 64 + (c0 - 64)) = make_float2(v0, v1);
            }
        }
    }
}

// ---------------------------------------------------------------------------
// Candidate GEMM + GRU update:
// c = tanh(X[128x256] @ Wc + bc + cbias); X = [in | rs | agg(in)/deg | agg(rs)/deg]
// out = u*state + (1-u)*c
// ---------------------------------------------------------------------------
__global__ void __launch_bounds__(256) cand_gemm(
    const float* __restrict__ inputs, const float* __restrict__ state,
    const float* __restrict__ bc, const float* __restrict__ cbias,
    float* __restrict__ out, int N) {
    int tid = threadIdx.x, lane = tid & 31, warp = tid >> 5;
    int g = lane >> 2, t = lane & 3;
    int nbase = blockIdx.x * 128;
    int row0 = nbase + warp * 16 + g;
    int row1 = row0 + 8;
    float id0 = (row0 < N) ? 1.0f / fmaxf(g_deg[row0], 1.0f) : 0.f;
    float id1 = (row1 < N) ? 1.0f / fmaxf(g_deg[row1], 1.0f) : 0.f;

    float acc[8][4];
    #pragma unroll
    for (int nt = 0; nt < 8; nt++)
        #pragma unroll
        for (int q = 0; q < 4; q++) acc[nt][q] = 0.f;

    #pragma unroll
    for (int kt = 0; kt < 16; kt++) {
        int kk = kt * 16 + t * 2;
        float2 p00 = loadXc(inputs, row0, kk,     id0, N);
        float2 p10 = loadXc(inputs, row1, kk,     id1, N);
        float2 p01 = loadXc(inputs, row0, kk + 8, id0, N);
        float2 p11 = loadXc(inputs, row1, kk + 8, id1, N);
        uint32_t ah[4], am[4];
        split2(p00, ah[0], am[0]);
        split2(p10, ah[1], am[1]);
        split2(p01, ah[2], am[2]);
        split2(p11, ah[3], am[3]);
        const uint4* fb = g_fragBc + (kt * 8) * 32 + lane;
        #pragma unroll
        for (int nt = 0; nt < 8; nt++) {
            uint4 f = __ldg(fb + nt * 32);
            mma_bf16(acc[nt], ah, f.x, f.y);
            mma_bf16(acc[nt], ah, f.z, f.w);
            mma_bf16(acc[nt], am, f.x, f.y);
        }
    }

    #pragma unroll
    for (int nt = 0; nt < 8; nt++) {
        int c0 = nt * 8 + t * 2;
        float b0 = __ldg(bc + c0) + __ldg(cbias + c0);
        float b1 = __ldg(bc + c0 + 1) + __ldg(cbias + c0 + 1);
        #pragma unroll
        for (int rr = 0; rr < 2; rr++) {
            int row = rr ? row1 : row0;
            if (row >= N) continue;
            float c_0 = tanhf(acc[nt][rr * 2 + 0] + b0);
            float c_1 = tanhf(acc[nt][rr * 2 + 1] + b1);
            float2 u2 = *(const float2*)(g_u + row * 64 + c0);
            float2 st = *(const float2*)(state + row * 64 + c0);
            float2 o;
            o.x = u2.x * st.x + (1.0f - u2.x) * c_0;
            o.y = u2.y * st.y + (1.0f - u2.y) * c_1;
            *(float2*)(out + row * 64 + c0) = o;
        }
    }
}

// ---------------------------------------------------------------------------
extern "C" void kernel_launch(void* const* d_in, const int* in_sizes, int n_in,
                              void* d_out, int out_size) {
    const float* inputs    = (const float*)d_in[0];
    const float* state     = (const float*)d_in[1];
    const int*   src       = (const int*)d_in[2];
    const int*   dst       = (const int*)d_in[3];
    const float* Wg_self   = (const float*)d_in[4];
    const float* Wg_neigh  = (const float*)d_in[5];
    const float* bg        = (const float*)d_in[6];
    const float* Wc_self   = (const float*)d_in[7];
    const float* Wc_neigh  = (const float*)d_in[8];
    const float* bc        = (const float*)d_in[9];
    const float* gate_bias = (const float*)d_in[10];
    const float* cand_bias = (const float*)d_in[11];
    float* out = (float*)d_out;

    int N = in_sizes[0] / 64;
    int E = in_sizes[2];

    void *p_agg1, *p_agg2, *p_deg;
    cudaGetSymbolAddress(&p_agg1, g_agg1);
    cudaGetSymbolAddress(&p_agg2, g_agg2);
    cudaGetSymbolAddress(&p_deg, g_deg);
    cudaMemsetAsync(p_agg1, 0, (size_t)N * 128 * sizeof(float));
    cudaMemsetAsync(p_agg2, 0, (size_t)N * 64 * sizeof(float));
    cudaMemsetAsync(p_deg, 0, (size_t)N * sizeof(float));

    prep_weights<<<48, 256>>>(Wg_self, Wg_neigh, Wc_self, Wc_neigh);
    {
        long long thr = (long long)E * 32;
        scatter1_kernel<<<(int)((thr + 255) / 256), 256>>>(inputs, state, src, dst, E);
    }
    int nblk = (N + 127) / 128;
    gate_gemm<<<nblk, 256>>>(inputs, state, bg, gate_bias, N);
    {
        long long thr = (long long)E * 16;
        scatter2_kernel<<<(int)((thr + 255) / 256), 256>>>(src, dst, E);
    }
    cand_gemm<<<nblk, 256>>>(inputs, state, bc, cand_bias, out, N);
}